// round 1
// baseline (speedup 1.0000x reference)
#include <cuda_runtime.h>
#include <math.h>

// Problem constants
#define BWIN   2048            // B * N_WIN windows
#define NTOK   64              // tokens per window
#define CDIM   256             // channels
#define MROWS  (BWIN * NTOK)   // 131072 total token rows
#define NBATCH 32              // distinct theta_max samples
#define SCALE  0.0625f         // 256^-0.5

// ---------------- scratch (device globals; no runtime allocation) -----------
__device__ float g_q [MROWS * CDIM];   // q * scale (bias folded)
__device__ float g_k [MROWS * CDIM];
__device__ float g_v [MROWS * CDIM];
__device__ float g_ao[MROWS * CDIM];   // attention output (pre-proj)
__device__ float g_bias[NBATCH * NTOK * NTOK]; // bias_phi + A_theta per batch

// ---------------- bias precompute -------------------------------------------
// bias_total[b][n][m] = a_p[ai]*cos(azf) + b_p[ai]*sin(azf)
//                     + a_r[ri]*cos(r*tm/64) + b_r[ri]*sin(r*tm/64)
__global__ void bias_kernel(const float* __restrict__ theta_max,
                            const float* __restrict__ a_p, const float* __restrict__ b_p,
                            const float* __restrict__ a_r, const float* __restrict__ b_r,
                            const int*   __restrict__ radius,
                            const int*   __restrict__ azimuth)
{
    const int b = blockIdx.x;
    const float tm = theta_max[b];
    const float azc = 2.0f * 3.14159265358979323846f / 64.0f;
    for (int i = threadIdx.x; i < NTOK * NTOK; i += blockDim.x) {
        int az = azimuth[i];
        int ai = az < 0 ? az + 15 : az;
        float azf = (float)az * azc;
        float phi = a_p[ai] * cosf(azf) + b_p[ai] * sinf(azf);
        int r = radius[i];
        int ri = r < 0 ? r + 15 : r;
        float rn = (float)r * tm * (1.0f / 64.0f);
        float th = a_r[ri] * cosf(rn) + b_r[ri] * sinf(rn);
        g_bias[b * (NTOK * NTOK) + i] = phi + th;
    }
}

// ---------------- tiled fp32 GEMM: C[m,n] = sum_k A[m,k] * W[n,k] ------------
// 64x64 block tile, BK=16, 256 threads, 4x4 register tile per thread.
// MODE 0: qkv epilogue (split into g_q*scale / g_k / g_v, + qkv_b)
// MODE 1: proj epilogue (write d_out, + proj_b), A = g_ao

__global__ __launch_bounds__(256)
void gemm_qkv_kernel(const float* __restrict__ A,       // x [131072,256]
                     const float* __restrict__ W,       // qkv_w [768,256]
                     const float* __restrict__ bias)    // qkv_b [768]
{
    __shared__ float As[16][64];
    __shared__ float Bs[16][64];

    const int tid = threadIdx.x;
    const int tx  = tid & 15, ty = tid >> 4;
    const int m0  = blockIdx.y << 6;
    const int n0  = blockIdx.x << 6;

    const int arow = tid >> 2;          // 0..63
    const int ac4  = (tid & 3) << 2;    // 0,4,8,12
    const int bcol = tid & 63;          // 0..63
    const int bk4  = (tid >> 6) << 2;   // 0,4,8,12

    const float* aptr = A + (m0 + arow) * 256 + ac4;
    const float* wptr = W + (n0 + bcol) * 256 + bk4;

    float acc[4][4] = {};

    for (int k0 = 0; k0 < 256; k0 += 16) {
        float4 av = *(const float4*)(aptr + k0);
        float4 wv = *(const float4*)(wptr + k0);
        __syncthreads();
        As[ac4 + 0][arow] = av.x; As[ac4 + 1][arow] = av.y;
        As[ac4 + 2][arow] = av.z; As[ac4 + 3][arow] = av.w;
        Bs[bk4 + 0][bcol] = wv.x; Bs[bk4 + 1][bcol] = wv.y;
        Bs[bk4 + 2][bcol] = wv.z; Bs[bk4 + 3][bcol] = wv.w;
        __syncthreads();
#pragma unroll
        for (int kk = 0; kk < 16; ++kk) {
            float4 a4 = *(const float4*)&As[kk][ty << 2];
            float4 b4 = *(const float4*)&Bs[kk][tx << 2];
            acc[0][0] += a4.x * b4.x; acc[0][1] += a4.x * b4.y;
            acc[0][2] += a4.x * b4.z; acc[0][3] += a4.x * b4.w;
            acc[1][0] += a4.y * b4.x; acc[1][1] += a4.y * b4.y;
            acc[1][2] += a4.y * b4.z; acc[1][3] += a4.y * b4.w;
            acc[2][0] += a4.z * b4.x; acc[2][1] += a4.z * b4.y;
            acc[2][2] += a4.z * b4.z; acc[2][3] += a4.z * b4.w;
            acc[3][0] += a4.w * b4.x; acc[3][1] += a4.w * b4.y;
            acc[3][2] += a4.w * b4.z; acc[3][3] += a4.w * b4.w;
        }
    }

    // epilogue: whole block maps to exactly one of q/k/v (n0 multiple of 64)
    const int gc = n0 + (tx << 2);
    float* buf; int off; float s;
    if (gc < 256)      { buf = g_q; off = 0;   s = SCALE; }
    else if (gc < 512) { buf = g_k; off = 256; s = 1.0f;  }
    else               { buf = g_v; off = 512; s = 1.0f;  }
    float b0 = bias[gc + 0], b1 = bias[gc + 1], b2 = bias[gc + 2], b3 = bias[gc + 3];
#pragma unroll
    for (int i = 0; i < 4; ++i) {
        int m = m0 + (ty << 2) + i;
        float4 o;
        o.x = (acc[i][0] + b0) * s;
        o.y = (acc[i][1] + b1) * s;
        o.z = (acc[i][2] + b2) * s;
        o.w = (acc[i][3] + b3) * s;
        *(float4*)&buf[m * 256 + gc - off] = o;
    }
}

__global__ __launch_bounds__(256)
void gemm_proj_kernel(const float* __restrict__ W,     // proj_w [256,256]
                      const float* __restrict__ bias,  // proj_b [256]
                      float* __restrict__ Cout)        // [131072,256]
{
    __shared__ float As[16][64];
    __shared__ float Bs[16][64];

    const int tid = threadIdx.x;
    const int tx  = tid & 15, ty = tid >> 4;
    const int m0  = blockIdx.y << 6;
    const int n0  = blockIdx.x << 6;

    const int arow = tid >> 2;
    const int ac4  = (tid & 3) << 2;
    const int bcol = tid & 63;
    const int bk4  = (tid >> 6) << 2;

    const float* aptr = g_ao + (m0 + arow) * 256 + ac4;
    const float* wptr = W + (n0 + bcol) * 256 + bk4;

    float acc[4][4] = {};

    for (int k0 = 0; k0 < 256; k0 += 16) {
        float4 av = *(const float4*)(aptr + k0);
        float4 wv = *(const float4*)(wptr + k0);
        __syncthreads();
        As[ac4 + 0][arow] = av.x; As[ac4 + 1][arow] = av.y;
        As[ac4 + 2][arow] = av.z; As[ac4 + 3][arow] = av.w;
        Bs[bk4 + 0][bcol] = wv.x; Bs[bk4 + 1][bcol] = wv.y;
        Bs[bk4 + 2][bcol] = wv.z; Bs[bk4 + 3][bcol] = wv.w;
        __syncthreads();
#pragma unroll
        for (int kk = 0; kk < 16; ++kk) {
            float4 a4 = *(const float4*)&As[kk][ty << 2];
            float4 b4 = *(const float4*)&Bs[kk][tx << 2];
            acc[0][0] += a4.x * b4.x; acc[0][1] += a4.x * b4.y;
            acc[0][2] += a4.x * b4.z; acc[0][3] += a4.x * b4.w;
            acc[1][0] += a4.y * b4.x; acc[1][1] += a4.y * b4.y;
            acc[1][2] += a4.y * b4.z; acc[1][3] += a4.y * b4.w;
            acc[2][0] += a4.z * b4.x; acc[2][1] += a4.z * b4.y;
            acc[2][2] += a4.z * b4.z; acc[2][3] += a4.z * b4.w;
            acc[3][0] += a4.w * b4.x; acc[3][1] += a4.w * b4.y;
            acc[3][2] += a4.w * b4.z; acc[3][3] += a4.w * b4.w;
        }
    }

    const int gc = n0 + (tx << 2);
    float b0 = bias[gc + 0], b1 = bias[gc + 1], b2 = bias[gc + 2], b3 = bias[gc + 3];
#pragma unroll
    for (int i = 0; i < 4; ++i) {
        int m = m0 + (ty << 2) + i;
        float4 o;
        o.x = acc[i][0] + b0;
        o.y = acc[i][1] + b1;
        o.z = acc[i][2] + b2;
        o.w = acc[i][3] + b3;
        *(float4*)&Cout[m * 256 + gc] = o;
    }
}

// ---------------- fused per-window attention ---------------------------------
// One block per window: S = (q*scale) k^T + bias -> softmax -> P @ v.
// Dynamic smem: Vs[64*256] + Ss[64*66] + As[16*64] + Bs[16*64] = 90624 B.
#define ATTN_SMEM_FLOATS (64*256 + 64*66 + 16*64 + 16*64)

__global__ __launch_bounds__(256)
void attn_kernel()
{
    extern __shared__ float sm[];
    float* Vs = sm;                       // 16384 floats [64][256]
    float* Ss = Vs + 64 * 256;            // 4224  floats [64][66]
    float* As = Ss + 64 * 66;             // 1024  floats [16][64]
    float* Bs = As + 16 * 64;             // 1024  floats [16][64]

    const int tid = threadIdx.x;
    const int tx  = tid & 15, ty = tid >> 4;
    const int w   = blockIdx.x;
    const int base = w * (NTOK * CDIM);

    // load V tile into smem (read once, used 4x in PV phase)
    {
        const float4* v4 = (const float4*)(g_v + base);
        float4* s4 = (float4*)Vs;
        for (int t = tid; t < (NTOK * CDIM) / 4; t += 256) s4[t] = v4[t];
    }

    // ---- S = qs @ k^T ----
    const int arow = tid >> 2;
    const int ac4  = (tid & 3) << 2;
    const int bcol = tid & 63;
    const int bk4  = (tid >> 6) << 2;
    const float* qptr = g_q + base + arow * 256 + ac4;
    const float* kptr = g_k + base + bcol * 256 + bk4;

    float acc[4][4] = {};
    for (int k0 = 0; k0 < 256; k0 += 16) {
        float4 av = *(const float4*)(qptr + k0);
        float4 kv = *(const float4*)(kptr + k0);
        __syncthreads();
        As[(ac4 + 0) * 64 + arow] = av.x; As[(ac4 + 1) * 64 + arow] = av.y;
        As[(ac4 + 2) * 64 + arow] = av.z; As[(ac4 + 3) * 64 + arow] = av.w;
        Bs[(bk4 + 0) * 64 + bcol] = kv.x; Bs[(bk4 + 1) * 64 + bcol] = kv.y;
        Bs[(bk4 + 2) * 64 + bcol] = kv.z; Bs[(bk4 + 3) * 64 + bcol] = kv.w;
        __syncthreads();
#pragma unroll
        for (int kk = 0; kk < 16; ++kk) {
            float4 a4 = *(const float4*)&As[kk * 64 + (ty << 2)];
            float4 b4 = *(const float4*)&Bs[kk * 64 + (tx << 2)];
            acc[0][0] += a4.x * b4.x; acc[0][1] += a4.x * b4.y;
            acc[0][2] += a4.x * b4.z; acc[0][3] += a4.x * b4.w;
            acc[1][0] += a4.y * b4.x; acc[1][1] += a4.y * b4.y;
            acc[1][2] += a4.y * b4.z; acc[1][3] += a4.y * b4.w;
            acc[2][0] += a4.z * b4.x; acc[2][1] += a4.z * b4.y;
            acc[2][2] += a4.z * b4.z; acc[2][3] += a4.z * b4.w;
            acc[3][0] += a4.w * b4.x; acc[3][1] += a4.w * b4.y;
            acc[3][2] += a4.w * b4.z; acc[3][3] += a4.w * b4.w;
        }
    }

    // add bias, stash S in smem
    {
        const float* bb = g_bias + (w >> 6) * (NTOK * NTOK);
#pragma unroll
        for (int i = 0; i < 4; ++i) {
            int n = (ty << 2) + i;
#pragma unroll
            for (int j = 0; j < 4; ++j) {
                int m = (tx << 2) + j;
                Ss[n * 66 + m] = acc[i][j] + bb[n * 64 + m];
            }
        }
    }
    __syncthreads();

    // ---- row softmax (64 rows, one thread each) ----
    if (tid < 64) {
        float* row = Ss + tid * 66;
        float mx = row[0];
#pragma unroll
        for (int m = 1; m < 64; ++m) mx = fmaxf(mx, row[m]);
        float s = 0.f;
#pragma unroll
        for (int m = 0; m < 64; ++m) { float e = __expf(row[m] - mx); row[m] = e; s += e; }
        float inv = 1.0f / s;
#pragma unroll
        for (int m = 0; m < 64; ++m) row[m] *= inv;
    }
    __syncthreads();

    // ---- out = P @ V ----
    float* outp = g_ao + base;
#pragma unroll
    for (int c0 = 0; c0 < 256; c0 += 64) {
        float o[4][4] = {};
#pragma unroll 8
        for (int kk = 0; kk < 64; ++kk) {
            float a0 = Ss[((ty << 2) + 0) * 66 + kk];
            float a1 = Ss[((ty << 2) + 1) * 66 + kk];
            float a2 = Ss[((ty << 2) + 2) * 66 + kk];
            float a3 = Ss[((ty << 2) + 3) * 66 + kk];
            float4 b4 = *(const float4*)&Vs[kk * 256 + c0 + (tx << 2)];
            o[0][0] += a0 * b4.x; o[0][1] += a0 * b4.y; o[0][2] += a0 * b4.z; o[0][3] += a0 * b4.w;
            o[1][0] += a1 * b4.x; o[1][1] += a1 * b4.y; o[1][2] += a1 * b4.z; o[1][3] += a1 * b4.w;
            o[2][0] += a2 * b4.x; o[2][1] += a2 * b4.y; o[2][2] += a2 * b4.z; o[2][3] += a2 * b4.w;
            o[3][0] += a3 * b4.x; o[3][1] += a3 * b4.y; o[3][2] += a3 * b4.z; o[3][3] += a3 * b4.w;
        }
#pragma unroll
        for (int i = 0; i < 4; ++i) {
            float4 ov; ov.x = o[i][0]; ov.y = o[i][1]; ov.z = o[i][2]; ov.w = o[i][3];
            *(float4*)&outp[((ty << 2) + i) * 256 + c0 + (tx << 2)] = ov;
        }
    }
}

// ---------------- launch ------------------------------------------------------
extern "C" void kernel_launch(void* const* d_in, const int* in_sizes, int n_in,
                              void* d_out, int out_size)
{
    const float* x         = (const float*)d_in[0];
    const float* theta_max = (const float*)d_in[1];
    const float* qkv_w     = (const float*)d_in[2];
    const float* qkv_b     = (const float*)d_in[3];
    const float* proj_w    = (const float*)d_in[4];
    const float* proj_b    = (const float*)d_in[5];
    const float* a_p       = (const float*)d_in[6];
    const float* b_p       = (const float*)d_in[7];
    const float* a_r       = (const float*)d_in[8];
    const float* b_r       = (const float*)d_in[9];
    const int*   radius    = (const int*)d_in[10];
    const int*   azimuth   = (const int*)d_in[11];
    float*       out       = (float*)d_out;

    // bias table [32,64,64]
    bias_kernel<<<NBATCH, 256>>>(theta_max, a_p, b_p, a_r, b_r, radius, azimuth);

    // qkv projection: [131072,256] x [256,768]
    gemm_qkv_kernel<<<dim3(768 / 64, MROWS / 64), 256>>>(x, qkv_w, qkv_b);

    // fused per-window attention
    const int smem_bytes = ATTN_SMEM_FLOATS * (int)sizeof(float);
    cudaFuncSetAttribute(attn_kernel, cudaFuncAttributeMaxDynamicSharedMemorySize, smem_bytes);
    attn_kernel<<<BWIN, 256, smem_bytes>>>();

    // output projection: [131072,256] x [256,256]
    gemm_proj_kernel<<<dim3(256 / 64, MROWS / 64), 256>>>(proj_w, proj_b, out);
}

// round 2
// speedup vs baseline: 3.0928x; 3.0928x over previous
#include <cuda_runtime.h>
#include <math.h>
#include <stdint.h>

#define BWIN   2048
#define NTOK   64
#define CDIM   256
#define MROWS  (BWIN * NTOK)
#define NBATCH 32
#define SCALE  0.0625f

// ---------------- scratch ----------------------------------------------------
__device__ float g_q [MROWS * CDIM];
__device__ float g_k [MROWS * CDIM];
__device__ float g_v [MROWS * CDIM];
__device__ float g_ao[MROWS * CDIM];
__device__ float g_bias[NBATCH * NTOK * NTOK];

// ---------------- tf32 helpers -----------------------------------------------
__device__ __forceinline__ uint32_t f2tf(float f) {
    uint32_t u; asm("cvt.rna.tf32.f32 %0, %1;" : "=r"(u) : "f"(f)); return u;
}
__device__ __forceinline__ void mma8(float* c, uint32_t a0, uint32_t a1, uint32_t a2, uint32_t a3,
                                     uint32_t b0, uint32_t b1) {
    asm volatile(
        "mma.sync.aligned.m16n8k8.row.col.f32.tf32.tf32.f32 "
        "{%0,%1,%2,%3},{%4,%5,%6,%7},{%8,%9},{%0,%1,%2,%3};"
        : "+f"(c[0]), "+f"(c[1]), "+f"(c[2]), "+f"(c[3])
        : "r"(a0), "r"(a1), "r"(a2), "r"(a3), "r"(b0), "r"(b1));
}

// ---------------- bias precompute ---------------------------------------------
__global__ void bias_kernel(const float* __restrict__ theta_max,
                            const float* __restrict__ a_p, const float* __restrict__ b_p,
                            const float* __restrict__ a_r, const float* __restrict__ b_r,
                            const int*   __restrict__ radius,
                            const int*   __restrict__ azimuth)
{
    const int b = blockIdx.x;
    const float tm = theta_max[b];
    const float azc = 2.0f * 3.14159265358979323846f / 64.0f;
    for (int i = threadIdx.x; i < NTOK * NTOK; i += blockDim.x) {
        int az = azimuth[i];
        int ai = az < 0 ? az + 15 : az;
        float azf = (float)az * azc;
        float phi = a_p[ai] * cosf(azf) + b_p[ai] * sinf(azf);
        int r = radius[i];
        int ri = r < 0 ? r + 15 : r;
        float rn = (float)r * tm * (1.0f / 64.0f);
        float th = a_r[ri] * cosf(rn) + b_r[ri] * sinf(rn);
        g_bias[b * (NTOK * NTOK) + i] = phi + th;
    }
}

// ---------------- tf32 GEMM: C[m,n] = sum_k A[m,k]*W[n,k] (+bias) -------------
// BM=128, BN=64, BK=32. 8 warps = 4(M)x2(N), warp tile 32x32.
// mode 0: qkv epilogue (split g_q*scale / g_k / g_v), mode 1: proj -> Cout.
__global__ __launch_bounds__(256)
void gemm_tf32_kernel(const float* __restrict__ A, const float* __restrict__ W,
                      const float* __restrict__ bias, float* __restrict__ Cout, int mode)
{
    __shared__ uint32_t As[128][36];   // [m][k], bank = (4m+k)%32 -> conflict-free
    __shared__ uint32_t Ws[64][36];    // [n][k]

    const int tid = threadIdx.x, lane = tid & 31, wid = tid >> 5;
    const int g = lane >> 2, tg = lane & 3;
    const int wm0 = (wid & 3) * 32, wn0 = (wid >> 2) * 32;
    const int m0 = blockIdx.y << 7, n0 = blockIdx.x << 6;

    float acc[2][4][4] = {};
    float4 ra[4]; float4 rb[2];

#pragma unroll
    for (int i = 0; i < 4; i++) { int lin = tid + (i << 8); int r = lin >> 3, c = (lin & 7) << 2;
        ra[i] = *(const float4*)(A + (m0 + r) * 256 + c); }
#pragma unroll
    for (int i = 0; i < 2; i++) { int lin = tid + (i << 8); int r = lin >> 3, c = (lin & 7) << 2;
        rb[i] = *(const float4*)(W + (n0 + r) * 256 + c); }

    for (int k0 = 0; k0 < 256; k0 += 32) {
        __syncthreads();
#pragma unroll
        for (int i = 0; i < 4; i++) { int lin = tid + (i << 8); int r = lin >> 3, c = (lin & 7) << 2;
            As[r][c]     = f2tf(ra[i].x); As[r][c + 1] = f2tf(ra[i].y);
            As[r][c + 2] = f2tf(ra[i].z); As[r][c + 3] = f2tf(ra[i].w); }
#pragma unroll
        for (int i = 0; i < 2; i++) { int lin = tid + (i << 8); int r = lin >> 3, c = (lin & 7) << 2;
            Ws[r][c]     = f2tf(rb[i].x); Ws[r][c + 1] = f2tf(rb[i].y);
            Ws[r][c + 2] = f2tf(rb[i].z); Ws[r][c + 3] = f2tf(rb[i].w); }
        __syncthreads();

        if (k0 < 224) {
#pragma unroll
            for (int i = 0; i < 4; i++) { int lin = tid + (i << 8); int r = lin >> 3, c = (lin & 7) << 2;
                ra[i] = *(const float4*)(A + (m0 + r) * 256 + k0 + 32 + c); }
#pragma unroll
            for (int i = 0; i < 2; i++) { int lin = tid + (i << 8); int r = lin >> 3, c = (lin & 7) << 2;
                rb[i] = *(const float4*)(W + (n0 + r) * 256 + k0 + 32 + c); }
        }

#pragma unroll
        for (int ks = 0; ks < 32; ks += 8) {
            uint32_t a[2][4], b[4][2];
#pragma unroll
            for (int mt = 0; mt < 2; mt++) {
                a[mt][0] = As[wm0 + mt * 16 + g][ks + tg];
                a[mt][1] = As[wm0 + mt * 16 + g + 8][ks + tg];
                a[mt][2] = As[wm0 + mt * 16 + g][ks + tg + 4];
                a[mt][3] = As[wm0 + mt * 16 + g + 8][ks + tg + 4];
            }
#pragma unroll
            for (int nt = 0; nt < 4; nt++) {
                b[nt][0] = Ws[wn0 + nt * 8 + g][ks + tg];
                b[nt][1] = Ws[wn0 + nt * 8 + g][ks + tg + 4];
            }
#pragma unroll
            for (int mt = 0; mt < 2; mt++)
#pragma unroll
                for (int nt = 0; nt < 4; nt++)
                    mma8(acc[mt][nt], a[mt][0], a[mt][1], a[mt][2], a[mt][3], b[nt][0], b[nt][1]);
        }
    }

    if (mode == 0) {
        const int region = n0; // whole 64-wide block stays within one of q/k/v
        float* buf; int off; float s;
        if (region < 256)      { buf = g_q; off = 0;   s = SCALE; }
        else if (region < 512) { buf = g_k; off = 256; s = 1.0f;  }
        else                   { buf = g_v; off = 512; s = 1.0f;  }
#pragma unroll
        for (int mt = 0; mt < 2; mt++)
#pragma unroll
            for (int nt = 0; nt < 4; nt++) {
                int col = n0 + wn0 + nt * 8 + 2 * tg;
                float b0 = bias[col], b1 = bias[col + 1];
                int r0 = m0 + wm0 + mt * 16 + g;
                float2 v0 = { (acc[mt][nt][0] + b0) * s, (acc[mt][nt][1] + b1) * s };
                float2 v1 = { (acc[mt][nt][2] + b0) * s, (acc[mt][nt][3] + b1) * s };
                *(float2*)(buf + (size_t)r0 * 256 + col - off)       = v0;
                *(float2*)(buf + (size_t)(r0 + 8) * 256 + col - off) = v1;
            }
    } else {
#pragma unroll
        for (int mt = 0; mt < 2; mt++)
#pragma unroll
            for (int nt = 0; nt < 4; nt++) {
                int col = n0 + wn0 + nt * 8 + 2 * tg;
                float b0 = bias[col], b1 = bias[col + 1];
                int r0 = m0 + wm0 + mt * 16 + g;
                float2 v0 = { acc[mt][nt][0] + b0, acc[mt][nt][1] + b1 };
                float2 v1 = { acc[mt][nt][2] + b0, acc[mt][nt][3] + b1 };
                *(float2*)(Cout + (size_t)r0 * 256 + col)       = v0;
                *(float2*)(Cout + (size_t)(r0 + 8) * 256 + col) = v1;
            }
    }
}

// ---------------- fused per-window attention (tf32 MMA) ------------------------
#define SS_STRIDE 68     // bank = (4m+k)%32 for fragment loads -> conflict-free
#define VS_STRIDE 264    // bank = (8k+n)%32 -> conflict-free
#define ATTN_SMEM_WORDS (64 * VS_STRIDE + 64 * SS_STRIDE + 64 * 36 * 2)

__global__ __launch_bounds__(256)
void attn_mma_kernel()
{
    extern __shared__ uint32_t sm[];
    uint32_t* Vs = sm;                        // [64][264] tf32
    uint32_t* Ss = Vs + 64 * VS_STRIDE;       // [64][68]  f32 then tf32(P)
    uint32_t* Qs = Ss + 64 * SS_STRIDE;       // [64][36]  tf32 chunk
    uint32_t* Ks = Qs + 64 * 36;              // [64][36]

    const int tid = threadIdx.x, lane = tid & 31, wid = tid >> 5;
    const int g = lane >> 2, tg = lane & 3;
    const int w = blockIdx.x;
    const size_t base = (size_t)w * NTOK * CDIM;

    // load V -> smem tf32 (used only in phase 2; sync before use is implied)
#pragma unroll
    for (int i = 0; i < 16; i++) {
        int lin = tid + (i << 8); int r = lin >> 6, c = (lin & 63) << 2;
        float4 v = *(const float4*)(g_v + base + r * 256 + c);
        Vs[r * VS_STRIDE + c]     = f2tf(v.x); Vs[r * VS_STRIDE + c + 1] = f2tf(v.y);
        Vs[r * VS_STRIDE + c + 2] = f2tf(v.z); Vs[r * VS_STRIDE + c + 3] = f2tf(v.w);
    }

    // ---- phase 1: S = (q*scale) @ k^T ----
    const int wm0 = (wid & 3) * 16, wn0 = (wid >> 2) * 32;
    float acc1[4][4] = {};
    float4 rq[2], rk[2];
#pragma unroll
    for (int i = 0; i < 2; i++) {
        int lin = tid + (i << 8); int r = lin >> 3, c = (lin & 7) << 2;
        rq[i] = *(const float4*)(g_q + base + r * 256 + c);
        rk[i] = *(const float4*)(g_k + base + r * 256 + c);
    }
    for (int k0 = 0; k0 < 256; k0 += 32) {
        __syncthreads();
#pragma unroll
        for (int i = 0; i < 2; i++) {
            int lin = tid + (i << 8); int r = lin >> 3, c = (lin & 7) << 2;
            Qs[r * 36 + c]     = f2tf(rq[i].x); Qs[r * 36 + c + 1] = f2tf(rq[i].y);
            Qs[r * 36 + c + 2] = f2tf(rq[i].z); Qs[r * 36 + c + 3] = f2tf(rq[i].w);
            Ks[r * 36 + c]     = f2tf(rk[i].x); Ks[r * 36 + c + 1] = f2tf(rk[i].y);
            Ks[r * 36 + c + 2] = f2tf(rk[i].z); Ks[r * 36 + c + 3] = f2tf(rk[i].w);
        }
        __syncthreads();
        if (k0 < 224) {
#pragma unroll
            for (int i = 0; i < 2; i++) {
                int lin = tid + (i << 8); int r = lin >> 3, c = (lin & 7) << 2;
                rq[i] = *(const float4*)(g_q + base + r * 256 + k0 + 32 + c);
                rk[i] = *(const float4*)(g_k + base + r * 256 + k0 + 32 + c);
            }
        }
#pragma unroll
        for (int ks = 0; ks < 32; ks += 8) {
            uint32_t a0 = Qs[(wm0 + g) * 36 + ks + tg];
            uint32_t a1 = Qs[(wm0 + g + 8) * 36 + ks + tg];
            uint32_t a2 = Qs[(wm0 + g) * 36 + ks + tg + 4];
            uint32_t a3 = Qs[(wm0 + g + 8) * 36 + ks + tg + 4];
#pragma unroll
            for (int nt = 0; nt < 4; nt++) {
                uint32_t b0 = Ks[(wn0 + nt * 8 + g) * 36 + ks + tg];
                uint32_t b1 = Ks[(wn0 + nt * 8 + g) * 36 + ks + tg + 4];
                mma8(acc1[nt], a0, a1, a2, a3, b0, b1);
            }
        }
    }

    // bias add + stash S (fp32) in Ss
    {
        const float* bb = g_bias + (w >> 6) * (NTOK * NTOK);
        float* Sf = (float*)Ss;
#pragma unroll
        for (int nt = 0; nt < 4; nt++) {
            int col = wn0 + nt * 8 + 2 * tg;
            int r0 = wm0 + g;
            Sf[r0 * SS_STRIDE + col]           = acc1[nt][0] + bb[r0 * 64 + col];
            Sf[r0 * SS_STRIDE + col + 1]       = acc1[nt][1] + bb[r0 * 64 + col + 1];
            Sf[(r0 + 8) * SS_STRIDE + col]     = acc1[nt][2] + bb[(r0 + 8) * 64 + col];
            Sf[(r0 + 8) * SS_STRIDE + col + 1] = acc1[nt][3] + bb[(r0 + 8) * 64 + col + 1];
        }
    }
    __syncthreads();

    // ---- softmax: 4 threads per row, quad shfl reduce; write P as tf32 ----
    {
        float* Sf = (float*)Ss;
        int r = tid >> 2, p = tid & 3;
        float v[16];
        float mx = -1e30f;
#pragma unroll
        for (int i = 0; i < 16; i++) { v[i] = Sf[r * SS_STRIDE + p + 4 * i]; mx = fmaxf(mx, v[i]); }
        mx = fmaxf(mx, __shfl_xor_sync(0xffffffffu, mx, 1));
        mx = fmaxf(mx, __shfl_xor_sync(0xffffffffu, mx, 2));
        float s = 0.f;
#pragma unroll
        for (int i = 0; i < 16; i++) { v[i] = __expf(v[i] - mx); s += v[i]; }
        s += __shfl_xor_sync(0xffffffffu, s, 1);
        s += __shfl_xor_sync(0xffffffffu, s, 2);
        float inv = 1.0f / s;
#pragma unroll
        for (int i = 0; i < 16; i++) Ss[r * SS_STRIDE + p + 4 * i] = f2tf(v[i] * inv);
    }
    __syncthreads();

    // ---- phase 2: out = P @ V ----
    {
        const int wn = wid * 32;
        float acc2[4][4][4] = {};
#pragma unroll
        for (int ks = 0; ks < 64; ks += 8) {
            uint32_t a[4][4];
#pragma unroll
            for (int mt = 0; mt < 4; mt++) {
                a[mt][0] = Ss[(mt * 16 + g) * SS_STRIDE + ks + tg];
                a[mt][1] = Ss[(mt * 16 + g + 8) * SS_STRIDE + ks + tg];
                a[mt][2] = Ss[(mt * 16 + g) * SS_STRIDE + ks + tg + 4];
                a[mt][3] = Ss[(mt * 16 + g + 8) * SS_STRIDE + ks + tg + 4];
            }
#pragma unroll
            for (int nt = 0; nt < 4; nt++) {
                uint32_t b0 = Vs[(ks + tg) * VS_STRIDE + wn + nt * 8 + g];
                uint32_t b1 = Vs[(ks + tg + 4) * VS_STRIDE + wn + nt * 8 + g];
#pragma unroll
                for (int mt = 0; mt < 4; mt++)
                    mma8(acc2[mt][nt], a[mt][0], a[mt][1], a[mt][2], a[mt][3], b0, b1);
            }
        }
#pragma unroll
        for (int mt = 0; mt < 4; mt++)
#pragma unroll
            for (int nt = 0; nt < 4; nt++) {
                int col = wn + nt * 8 + 2 * tg, r0 = mt * 16 + g;
                float2 v0 = { acc2[mt][nt][0], acc2[mt][nt][1] };
                float2 v1 = { acc2[mt][nt][2], acc2[mt][nt][3] };
                *(float2*)(g_ao + base + r0 * 256 + col)       = v0;
                *(float2*)(g_ao + base + (r0 + 8) * 256 + col) = v1;
            }
    }
}

// ---------------- launch -------------------------------------------------------
extern "C" void kernel_launch(void* const* d_in, const int* in_sizes, int n_in,
                              void* d_out, int out_size)
{
    const float* x         = (const float*)d_in[0];
    const float* theta_max = (const float*)d_in[1];
    const float* qkv_w     = (const float*)d_in[2];
    const float* qkv_b     = (const float*)d_in[3];
    const float* proj_w    = (const float*)d_in[4];
    const float* proj_b    = (const float*)d_in[5];
    const float* a_p       = (const float*)d_in[6];
    const float* b_p       = (const float*)d_in[7];
    const float* a_r       = (const float*)d_in[8];
    const float* b_r       = (const float*)d_in[9];
    const int*   radius    = (const int*)d_in[10];
    const int*   azimuth   = (const int*)d_in[11];
    float*       out       = (float*)d_out;

    bias_kernel<<<NBATCH, 256>>>(theta_max, a_p, b_p, a_r, b_r, radius, azimuth);

    float* g_ao_ptr = nullptr;
    cudaGetSymbolAddress((void**)&g_ao_ptr, g_ao);

    // qkv: [131072,256] x [256,768]
    gemm_tf32_kernel<<<dim3(768 / 64, MROWS / 128), 256>>>(x, qkv_w, qkv_b, nullptr, 0);

    // fused attention
    const int smem_bytes = ATTN_SMEM_WORDS * (int)sizeof(uint32_t);
    cudaFuncSetAttribute(attn_mma_kernel, cudaFuncAttributeMaxDynamicSharedMemorySize, smem_bytes);
    attn_mma_kernel<<<BWIN, 256, smem_bytes>>>();

    // proj: [131072,256] x [256,256]
    gemm_tf32_kernel<<<dim3(256 / 64, MROWS / 128), 256>>>(g_ao_ptr, proj_w, proj_b, out, 1);
}